// round 2
// baseline (speedup 1.0000x reference)
#include <cuda_runtime.h>

// DConv: channel-shifted 3x3 conv, B=16, C_IN=C_OUT=64, H=W=160, fp32.
// out[b,o,i,j] = sum_{c,ky,kx} w[o,c,ky,kx] * xz[b,c, i+ky-1-dy_c, j+kx-1-dx_c]
// where xz zero-pads outside [0,160)^2 and (dx,dy) depends on c%5:
//   0:(0,0)  1:(1,0)  2:(0,1)  3:(-1,0)  4:(0,-1)
// (The %Hp wrap in the reference only ever hits the zero-pad rows/cols, so it
//  is exactly equivalent to this shifted zero-padded conv.)

#define H 160
#define W 160
#define CIN 64
#define COUT 64
#define TILE_H 32
#define TILE_W 32
#define O_PER_BLOCK 8
#define THREADS 128

// smem x tile: 34x34 valid, row stride 36
#define SX_STRIDE 36

__global__ __launch_bounds__(THREADS, 3)
void dconv_kernel(const float* __restrict__ x,
                  const float* __restrict__ w,
                  float* __restrict__ out)
{
    __shared__ float s_x[34 * SX_STRIDE];
    __shared__ float s_w[CIN * 9 * O_PER_BLOCK];   // [c][tap][o]

    const int tile_x = blockIdx.x * TILE_W;
    const int tile_y = blockIdx.y * TILE_H;
    const int b  = blockIdx.z >> 3;
    const int og = (blockIdx.z & 7) * O_PER_BLOCK;

    const int tid = threadIdx.x;

    // Stage weights for this o-group: s_w[c*72 + t*8 + ol] = w[(og+ol), c, t]
    #pragma unroll 4
    for (int idx = tid; idx < CIN * 9 * O_PER_BLOCK; idx += THREADS) {
        int ol = idx & (O_PER_BLOCK - 1);
        int t  = (idx >> 3) % 9;
        int c  = idx / (9 * O_PER_BLOCK);
        s_w[idx] = w[((og + ol) * CIN + c) * 9 + t];
    }

    // thread micro-tile: 4 rows x 2 cols
    const int tx = tid & 15;       // 0..15 -> col pair
    const int ty = tid >> 4;       // 0..7  -> row group
    const int s0 = tx * 2;
    const int r0 = ty * 4;

    float acc[O_PER_BLOCK][4][2];
    #pragma unroll
    for (int o = 0; o < O_PER_BLOCK; ++o)
        #pragma unroll
        for (int r = 0; r < 4; ++r) {
            acc[o][r][0] = 0.f;
            acc[o][r][1] = 0.f;
        }

    const float* xb = x + (size_t)b * CIN * H * W;

    int m = 0;   // c % 5, tracked incrementally
    for (int c = 0; c < CIN; ++c) {
        // shift for this channel
        int dy = (m == 2) ? 1 : ((m == 4) ? -1 : 0);
        int dx = (m == 1) ? 1 : ((m == 3) ? -1 : 0);
        m = (m == 4) ? 0 : m + 1;

        const float* xc = xb + (size_t)c * H * W;
        const int row_off = tile_y - 1 - dy;
        const int col_off = tile_x - 1 - dx;

        __syncthreads();   // previous iteration's reads done before overwrite
        // s_x[p][q] = xz[row_off + p, col_off + q], p,q in [0,34)
        #pragma unroll
        for (int k = 0; k < 10; ++k) {
            int idx = tid + k * THREADS;
            if (idx < 34 * 34) {
                int p = idx / 34;
                int q = idx - p * 34;
                int ii = row_off + p;
                int jj = col_off + q;
                float v = 0.f;
                if ((unsigned)ii < (unsigned)H && (unsigned)jj < (unsigned)W)
                    v = xc[ii * W + jj];
                s_x[p * SX_STRIDE + q] = v;
            }
        }
        __syncthreads();

        // register window: 6 rows x 4 cols
        float win[6][4];
        #pragma unroll
        for (int ry = 0; ry < 6; ++ry)
            #pragma unroll
            for (int sx = 0; sx < 4; ++sx)
                win[ry][sx] = s_x[(r0 + ry) * SX_STRIDE + (s0 + sx)];

        const float* wc = &s_w[c * 9 * O_PER_BLOCK];
        #pragma unroll
        for (int ky = 0; ky < 3; ++ky)
            #pragma unroll
            for (int kx = 0; kx < 3; ++kx) {
                const int t = ky * 3 + kx;
                #pragma unroll
                for (int o = 0; o < O_PER_BLOCK; ++o) {
                    const float wv = wc[t * O_PER_BLOCK + o];
                    #pragma unroll
                    for (int r = 0; r < 4; ++r) {
                        acc[o][r][0] = fmaf(wv, win[r + ky][0 + kx], acc[o][r][0]);
                        acc[o][r][1] = fmaf(wv, win[r + ky][1 + kx], acc[o][r][1]);
                    }
                }
            }
    }

    // write out: float2 stores, coalesced along s0
    #pragma unroll
    for (int o = 0; o < O_PER_BLOCK; ++o) {
        #pragma unroll
        for (int r = 0; r < 4; ++r) {
            float2 v = make_float2(acc[o][r][0], acc[o][r][1]);
            size_t off = (((size_t)b * COUT + (og + o)) * H + (tile_y + r0 + r)) * W
                         + (tile_x + s0);
            *reinterpret_cast<float2*>(out + off) = v;
        }
    }
}

extern "C" void kernel_launch(void* const* d_in, const int* in_sizes, int n_in,
                              void* d_out, int out_size)
{
    const float* x = (const float*)d_in[0];
    const float* w = (const float*)d_in[1];
    float* out = (float*)d_out;

    dim3 grid(W / TILE_W, H / TILE_H, 16 * (COUT / O_PER_BLOCK));  // 5 x 5 x 128
    dconv_kernel<<<grid, THREADS>>>(x, w, out);
}

// round 3
// speedup vs baseline: 1.0785x; 1.0785x over previous
#include <cuda_runtime.h>

// DConv: channel-shifted 3x3 conv, B=16, C_IN=C_OUT=64, H=W=160, fp32.
// out[b,o,i,j] = sum_{c,ky,kx} w[o,c,ky,kx] * xz[b,c, i+ky-1-dy_c, j+kx-1-dx_c]
// xz zero-pads outside [0,160)^2; (dx,dy) from c%5:
//   0:(0,0)  1:(1,0)  2:(0,1)  3:(-1,0)  4:(0,-1)
//
// R2: software-pipelined channel loop (double-buffered smem tile, register
// prefetch of next channel), float2 window loads, float4 weight loads,
// hoisted load geometry. One __syncthreads per channel.

#define H 160
#define W 160
#define CIN 64
#define COUT 64
#define TILE_H 32
#define TILE_W 32
#define O_PER_BLOCK 8
#define THREADS 128
#define SX_STRIDE 36           // 34 valid cols + 2 pad
#define TILE_ELEMS (34 * 34)   // 1156
#define LD_PER_THREAD 10       // ceil(1156/128)

__global__ __launch_bounds__(THREADS, 3)
void dconv_kernel(const float* __restrict__ x,
                  const float* __restrict__ w,
                  float* __restrict__ out)
{
    __shared__ float s_x[2][34 * SX_STRIDE];
    __shared__ float s_w[CIN * 9 * O_PER_BLOCK];   // [c][tap][o], 18 KB

    const int tile_x = blockIdx.x * TILE_W;
    const int tile_y = blockIdx.y * TILE_H;
    const int b  = blockIdx.z >> 3;
    const int og = (blockIdx.z & 7) * O_PER_BLOCK;

    const int tid = threadIdx.x;

    // ---- stage weights for this o-group: s_w[c*72 + t*8 + ol] = w[(og+ol), c, t]
    #pragma unroll 4
    for (int idx = tid; idx < CIN * 9 * O_PER_BLOCK; idx += THREADS) {
        int ol = idx & (O_PER_BLOCK - 1);
        int t  = (idx >> 3) % 9;
        int c  = idx / (9 * O_PER_BLOCK);
        s_w[idx] = w[((og + ol) * CIN + c) * 9 + t];
    }

    // ---- channel-invariant load geometry (p,q in the 34x34 tile) ----
    int pk[LD_PER_THREAD], qk[LD_PER_THREAD];
    bool vk[LD_PER_THREAD];
    #pragma unroll
    for (int k = 0; k < LD_PER_THREAD; ++k) {
        int idx = tid + k * THREADS;
        vk[k] = (idx < TILE_ELEMS);
        int p = idx / 34;
        int q = idx - p * 34;
        pk[k] = p;
        qk[k] = q;
    }

    const float* xb = x + (size_t)b * CIN * H * W;

    // thread micro-tile: 4 rows x 2 cols
    const int tx = tid & 15;
    const int ty = tid >> 4;
    const int s0 = tx * 2;
    const int r0 = ty * 4;

    float acc[O_PER_BLOCK][4][2];
    #pragma unroll
    for (int o = 0; o < O_PER_BLOCK; ++o)
        #pragma unroll
        for (int r = 0; r < 4; ++r) {
            acc[o][r][0] = 0.f;
            acc[o][r][1] = 0.f;
        }

    // shift table via c%5, tracked incrementally
    // m: 0:(0,0) 1:(1,0) 2:(0,1) 3:(-1,0) 4:(0,-1)  -> (dx,dy)
    float ld[LD_PER_THREAD];

    // ---- prologue: load channel 0 into registers, store to buf 0 ----
    {
        const float* xc = xb;                 // c=0 -> dx=dy=0
        const int row_off = tile_y - 1;
        const int col_off = tile_x - 1;
        #pragma unroll
        for (int k = 0; k < LD_PER_THREAD; ++k) {
            int ii = row_off + pk[k];
            int jj = col_off + qk[k];
            float v = 0.f;
            if (vk[k] && (unsigned)ii < (unsigned)H && (unsigned)jj < (unsigned)W)
                v = xc[ii * W + jj];
            ld[k] = v;
        }
        #pragma unroll
        for (int k = 0; k < LD_PER_THREAD; ++k)
            if (vk[k]) s_x[0][pk[k] * SX_STRIDE + qk[k]] = ld[k];
    }
    __syncthreads();   // weights + buf0 visible

    int mn = 1;  // (c+1) % 5 for the prefetch channel
    for (int c = 0; c < CIN; ++c) {
        // ---- prefetch channel c+1 into registers (overlaps with compute) ----
        if (c < CIN - 1) {
            int dy = (mn == 2) ? 1 : ((mn == 4) ? -1 : 0);
            int dx = (mn == 1) ? 1 : ((mn == 3) ? -1 : 0);
            mn = (mn == 4) ? 0 : mn + 1;
            const float* xc = xb + (size_t)(c + 1) * H * W;
            const int row_off = tile_y - 1 - dy;
            const int col_off = tile_x - 1 - dx;
            #pragma unroll
            for (int k = 0; k < LD_PER_THREAD; ++k) {
                int ii = row_off + pk[k];
                int jj = col_off + qk[k];
                float v = 0.f;
                if (vk[k] && (unsigned)ii < (unsigned)H && (unsigned)jj < (unsigned)W)
                    v = xc[ii * W + jj];
                ld[k] = v;
            }
        }

        // ---- compute channel c from buf[c&1] ----
        const float* bx = s_x[c & 1];
        float win[6][4];
        #pragma unroll
        for (int ry = 0; ry < 6; ++ry) {
            float2 a = *reinterpret_cast<const float2*>(&bx[(r0 + ry) * SX_STRIDE + s0]);
            float2 bb = *reinterpret_cast<const float2*>(&bx[(r0 + ry) * SX_STRIDE + s0 + 2]);
            win[ry][0] = a.x;  win[ry][1] = a.y;
            win[ry][2] = bb.x; win[ry][3] = bb.y;
        }

        const float4* wc4 = reinterpret_cast<const float4*>(&s_w[c * 9 * O_PER_BLOCK]);
        #pragma unroll
        for (int t = 0; t < 9; ++t) {
            const int ky = t / 3;
            const int kx = t - ky * 3;
            float4 wa = wc4[2 * t];
            float4 wb = wc4[2 * t + 1];
            float wv[O_PER_BLOCK] = {wa.x, wa.y, wa.z, wa.w, wb.x, wb.y, wb.z, wb.w};
            #pragma unroll
            for (int o = 0; o < O_PER_BLOCK; ++o) {
                #pragma unroll
                for (int r = 0; r < 4; ++r) {
                    acc[o][r][0] = fmaf(wv[o], win[r + ky][0 + kx], acc[o][r][0]);
                    acc[o][r][1] = fmaf(wv[o], win[r + ky][1 + kx], acc[o][r][1]);
                }
            }
        }

        // ---- commit prefetched channel to the other buffer ----
        if (c < CIN - 1) {
            float* nb = s_x[(c + 1) & 1];
            #pragma unroll
            for (int k = 0; k < LD_PER_THREAD; ++k)
                if (vk[k]) nb[pk[k] * SX_STRIDE + qk[k]] = ld[k];
            __syncthreads();
        }
    }

    // ---- write out: float2 stores, coalesced along s0 ----
    #pragma unroll
    for (int o = 0; o < O_PER_BLOCK; ++o) {
        #pragma unroll
        for (int r = 0; r < 4; ++r) {
            float2 v = make_float2(acc[o][r][0], acc[o][r][1]);
            size_t off = (((size_t)b * COUT + (og + o)) * H + (tile_y + r0 + r)) * W
                         + (tile_x + s0);
            *reinterpret_cast<float2*>(out + off) = v;
        }
    }
}

extern "C" void kernel_launch(void* const* d_in, const int* in_sizes, int n_in,
                              void* d_out, int out_size)
{
    const float* x = (const float*)d_in[0];
    const float* w = (const float*)d_in[1];
    float* out = (float*)d_out;

    dim3 grid(W / TILE_W, H / TILE_H, 16 * (COUT / O_PER_BLOCK));  // 5 x 5 x 128
    dconv_kernel<<<grid, THREADS>>>(x, w, out);
}

// round 5
// speedup vs baseline: 1.6566x; 1.5360x over previous
#include <cuda_runtime.h>
#include <cstdint>

// DConv via implicit GEMM on legacy tensor-core path (mma.sync tf32 — the
// tcgen05 path is blocked: harness compiles via compute_103 (no 'a'), which
// rejects tcgen05/TMEM instructions in ptxas).
//
// Per output row y of image b:
//   D[o][x] = sum_{ky,c,kx} W[o][c][ky][kx] * XS[c][y-1+ky][x+kx-1]
// XS applies the per-channel (c%5) shift and zero pad:
//   (dx,dy): 0:(0,0) 1:(1,0) 2:(0,1) 3:(-1,0) 4:(0,-1)
// GEMM: M=64 (out ch), N=160 (pixels), K=576 streamed in 8 chunks of 72
// (= 3 ky x 8 c x 3 kx). mma.sync.m16n8k8 tf32, fp32 accum.
// 8 warps = 4(M) x 2(N); warp tile m16 x n80 (10 n8 frags), acc 40 regs.

#define HH 160
#define WW 160
#define CIN 64
#define COUT 64
#define THREADS 256
#define NCHUNK 8

// smem layout (dynamic)
#define DESC_OFF 0                    // 576 x int2 = 4608
#define WOFF_OFF 4608                 // 72 x int  = 288
#define BUF_OFF  5120
#define A_BYTES  18432                // 4 mfrag x 9 ks x 32 lane x 16B
#define B_BYTES  46080                // 20 nfrag x 9 ks x 32 lane x 8B
#define BUF_STRIDE (A_BYTES + B_BYTES)        // 64512
#define SMEM_TOTAL (BUF_OFF + 2 * BUF_STRIDE) // 134144

__device__ __forceinline__ uint32_t f2tf(float f) {
    uint32_t r;
    asm("cvt.rna.tf32.f32 %0, %1;" : "=r"(r) : "f"(f));
    return r;
}

__device__ __forceinline__ void mma_tf32(float* c, uint4 a, uint2 b) {
    asm volatile(
        "mma.sync.aligned.m16n8k8.row.col.f32.tf32.tf32.f32 "
        "{%0,%1,%2,%3}, {%4,%5,%6,%7}, {%8,%9}, {%0,%1,%2,%3};"
        : "+f"(c[0]), "+f"(c[1]), "+f"(c[2]), "+f"(c[3])
        : "r"(a.x), "r"(a.y), "r"(a.z), "r"(a.w), "r"(b.x), "r"(b.y));
}

extern __shared__ char smem[];

__global__ __launch_bounds__(THREADS, 1)
void dconv_mma_kernel(const float* __restrict__ x,
                      const float* __restrict__ w,
                      float* __restrict__ out)
{
    const int y   = blockIdx.x;
    const int b   = blockIdx.y;
    const int tid = threadIdx.x;
    const int lane = tid & 31;
    const int wid  = tid >> 5;
    const int g = lane >> 2;      // groupID
    const int t = lane & 3;       // threadID_in_group
    const int fm = wid & 3;       // M-warp (o block of 16)
    const int wn = wid >> 2;      // N-warp (x block of 80)

    int2* desc = (int2*)(smem + DESC_OFF);     // per global-K row
    int*  woff = (int*)(smem + WOFF_OFF);      // k_local -> weight tap offset

    // ---- prologue: descriptor tables (CTA-uniform geometry) ----
    for (int k = tid; k < 576; k += THREADS) {
        int ch = k / 72;
        int kl = k - ch * 72;
        int ky = kl / 24;
        int r2 = kl - ky * 24;
        int cl = r2 / 3;
        int kx = r2 - cl * 3;
        int c  = ch * 8 + cl;
        int m5 = c % 5;
        int dy = (m5 == 2) ? 1 : ((m5 == 4) ? -1 : 0);
        int dx = (m5 == 1) ? 1 : ((m5 == 3) ? -1 : 0);
        int gy  = y - 1 + ky - dy;
        int off = kx - 1 - dx;                         // in [-2, 2]
        int rowBase = (c * (HH * WW) + gy * WW + off) * 4;   // bytes
        int flags = (((unsigned)gy < (unsigned)HH) ? 256 : 0) | (off + 2);
        desc[k] = make_int2(rowBase, flags);
    }
    if (tid < 72) {
        int ky = tid / 24;
        int r2 = tid - ky * 24;
        int cl = r2 / 3;
        int kx = r2 - cl * 3;
        woff[tid] = cl * 9 + ky * 3 + kx;
    }
    __syncthreads();

    const char* xbp = (const char*)(x + (size_t)b * CIN * HH * WW);

    float acc[10][4];
    #pragma unroll
    for (int fn = 0; fn < 10; ++fn)
        #pragma unroll
        for (int i = 0; i < 4; ++i) acc[fn][i] = 0.f;

    for (int ch = 0; ch < NCHUNK; ++ch) {
        char* bufA = smem + BUF_OFF + (ch & 1) * BUF_STRIDE;
        char* bufB = bufA + A_BYTES;
        const int cb9 = ch * 8 * 9;                // c0 * 9 (weight col base)
        const int2* dch = desc + ch * 72;

        // ---- stage A: 1152 slots of 16B; thread does slots tid + i*256 ----
        float av[5][4];
        int   sA[5];
        #pragma unroll
        for (int i = 0; i < 5; ++i) {
            int s = tid + i * THREADS;
            sA[i] = s;
            int q = s >> 5;                         // (fm,ks) pair, q < 40
            int fmS = q / 9;
            int ks  = q - fmS * 9;
            int k0  = ks * 8 + t;                   // <= 67
            int w0  = woff[k0];
            int w1  = woff[k0 + 4];
            int m0  = fmS * 16 + g;
            const float* wr0 = w + m0 * (CIN * 9) + cb9;
            const float* wr1 = wr0 + 8 * (CIN * 9);
            if (s < 1152) {
                av[i][0] = wr0[w0];
                av[i][1] = wr1[w0];
                av[i][2] = wr0[w1];
                av[i][3] = wr1[w1];
            }
        }

        // ---- stage B: 180 (fn,ks) pairs x 32 lanes; warp does p = wid + i*8 ----
        float bv[23][2];
        #pragma unroll
        for (int i = 0; i < 23; ++i) {
            int p = wid + i * 8;                    // < 184
            bool ok = p < 180;
            int fnG = p / 9;
            int ks  = p - fnG * 9;
            int x0  = fnG * 8 + g;                  // pixel (frag col = g)
            int k0  = ks * 8 + t;
            int2 d0 = dch[k0];
            int2 d1 = dch[k0 + 4];
            int gx0 = x0 + (d0.y & 255) - 2;
            int gx1 = x0 + (d1.y & 255) - 2;
            bool p0 = ok && (d0.y & 256) && (unsigned)gx0 < (unsigned)WW;
            bool p1 = ok && (d1.y & 256) && (unsigned)gx1 < (unsigned)WW;
            float v0 = p0 ? *(const float*)(xbp + d0.x + x0 * 4) : 0.f;
            float v1 = p1 ? *(const float*)(xbp + d1.x + x0 * 4) : 0.f;
            bv[i][0] = v0;
            bv[i][1] = v1;
        }

        // ---- commit staged data (cvt to tf32, vector STS) ----
        #pragma unroll
        for (int i = 0; i < 5; ++i) {
            if (sA[i] < 1152) {
                uint4 v = make_uint4(f2tf(av[i][0]), f2tf(av[i][1]),
                                     f2tf(av[i][2]), f2tf(av[i][3]));
                *(uint4*)(bufA + sA[i] * 16) = v;
            }
        }
        #pragma unroll
        for (int i = 0; i < 23; ++i) {
            int p = wid + i * 8;
            if (p < 180) {
                uint2 v = make_uint2(f2tf(bv[i][0]), f2tf(bv[i][1]));
                *(uint2*)(bufB + p * 256 + lane * 8) = v;
            }
        }

        __syncthreads();

        // ---- compute: 9 k-steps x 10 n-frags of m16n8k8 ----
        #pragma unroll
        for (int ks = 0; ks < 9; ++ks) {
            uint4 a = *(const uint4*)(bufA + ((fm * 9 + ks) * 32 + lane) * 16);
            #pragma unroll
            for (int fn = 0; fn < 10; ++fn) {
                uint2 bb = *(const uint2*)(bufB +
                              (((wn * 10 + fn) * 9 + ks) * 32 + lane) * 8);
                mma_tf32(acc[fn], a, bb);
            }
        }
        // next iteration stages the other buffer; the sync above guarantees
        // every warp finished the chunk that used it.
    }

    // ---- epilogue: D[m][x] -> out[b][m][y][x] ----
    #pragma unroll
    for (int fn = 0; fn < 10; ++fn) {
        int xg = wn * 80 + fn * 8 + t * 2;
        int m0 = fm * 16 + g;
        float* o0 = out + (((size_t)b * COUT + m0) * HH + y) * WW + xg;
        float* o1 = o0 + 8 * HH * WW;
        *(float2*)o0 = make_float2(acc[fn][0], acc[fn][1]);
        *(float2*)o1 = make_float2(acc[fn][2], acc[fn][3]);
    }
}

extern "C" void kernel_launch(void* const* d_in, const int* in_sizes, int n_in,
                              void* d_out, int out_size)
{
    const float* x = (const float*)d_in[0];
    const float* w = (const float*)d_in[1];
    float* out = (float*)d_out;

    cudaFuncSetAttribute(dconv_mma_kernel,
                         cudaFuncAttributeMaxDynamicSharedMemorySize, SMEM_TOTAL);

    dim3 grid(HH, 16);
    dconv_mma_kernel<<<grid, THREADS, SMEM_TOTAL>>>(x, w, out);
}